// round 2
// baseline (speedup 1.0000x reference)
#include <cuda_runtime.h>
#include <stdint.h>

// Problem constants (fixed shapes per reference)
#define NN 50000            // nodes
#define DD 64               // feature dim
#define DV4 16              // float4s per row

// Scratch (device globals -- no allocation allowed).
// NOTE: these symbols are ONLY referenced inside device code; taking their
// address from host code yields the host shadow symbol (R1 bug).
__device__ float g_tmpA[NN * DD];   // scaled source / acc2
__device__ float g_tmpB[NN * DD];   // acc1 / gemm output
__device__ float g_degO[NN];
__device__ float g_degI[NN];
__device__ float g_invO[NN];
__device__ float g_invI[NN];

__device__ __forceinline__ void red_add_v4(float* addr, float4 v) {
    asm volatile("red.global.add.v4.f32 [%0], {%1,%2,%3,%4};"
                 :: "l"(addr), "f"(v.x), "f"(v.y), "f"(v.z), "f"(v.w)
                 : "memory");
}

// ---------------------------------------------------------------------------
// 1) zero: acc1 (tmpB), d_out, degree arrays
__global__ void k_zero(float4* __restrict__ out4) {
    int tid = blockIdx.x * blockDim.x + threadIdx.x;
    if (tid < NN * DV4) {
        float4 z = make_float4(0.f, 0.f, 0.f, 0.f);
        reinterpret_cast<float4*>(g_tmpB)[tid] = z;
        out4[tid] = z;
        if (tid < NN) { g_degO[tid] = 0.f; g_degI[tid] = 0.f; }
    }
}

// 2) degrees
__global__ void k_degree(const int* __restrict__ src, const int* __restrict__ dst, int E) {
    int e = blockIdx.x * blockDim.x + threadIdx.x;
    if (e < E) {
        atomicAdd(&g_degO[src[e]], 1.0f);
        atomicAdd(&g_degI[dst[e]], 1.0f);
    }
}

// 3) inv-sqrt degrees + tmpA = x * invO   (full overwrite of tmpA)
__global__ void k_scale_x(const float4* __restrict__ x4) {
    int tid = blockIdx.x * blockDim.x + threadIdx.x;
    if (tid >= NN * DV4) return;
    int n = tid >> 4, c = tid & 15;
    float io = rsqrtf(fmaxf(g_degO[n], 1.0f));
    if (c == 0) {
        g_invO[n] = io;
        g_invI[n] = rsqrtf(fmaxf(g_degI[n], 1.0f));
    }
    float4 v = x4[tid];
    v.x *= io; v.y *= io; v.z *= io; v.w *= io;
    reinterpret_cast<float4*>(g_tmpA)[n * DV4 + c] = v;
}

// 4) layer-0 scatter: tmpB[dst] += tmpA[src]   (vec4 atomics)
__global__ void k_scatter1(const int* __restrict__ src, const int* __restrict__ dst, int E) {
    int tid = blockIdx.x * blockDim.x + threadIdx.x;
    if (tid >= E * DV4) return;
    int e = tid >> 4, c = tid & 15;
    int s = __ldg(src + e);
    int d = __ldg(dst + e);
    float4 v = *(reinterpret_cast<const float4*>(g_tmpA) + s * DV4 + c);
    red_add_v4(g_tmpB + (size_t)d * DD + c * 4, v);
}

// 5) tmpB = acc1 * invI * invO  (layer-0 in-norm fused with layer-1 out-scale),
//    and rezero tmpA so it can serve as acc2.
__global__ void k_rescale_rezero() {
    int tid = blockIdx.x * blockDim.x + threadIdx.x;
    if (tid >= NN * DV4) return;
    int n = tid >> 4;
    float sc = g_invI[n] * g_invO[n];
    float4 v = reinterpret_cast<const float4*>(g_tmpB)[tid];
    v.x *= sc; v.y *= sc; v.z *= sc; v.w *= sc;
    reinterpret_cast<float4*>(g_tmpB)[tid] = v;
    reinterpret_cast<float4*>(g_tmpA)[tid] = make_float4(0.f, 0.f, 0.f, 0.f);
}

// 6) layer-1 scatter: tmpA[dst] += tmpB[src]
__global__ void k_scatter2(const int* __restrict__ src, const int* __restrict__ dst, int E) {
    int tid = blockIdx.x * blockDim.x + threadIdx.x;
    if (tid >= E * DV4) return;
    int e = tid >> 4, c = tid & 15;
    int s = __ldg(src + e);
    int d = __ldg(dst + e);
    float4 v = *(reinterpret_cast<const float4*>(g_tmpB) + s * DV4 + c);
    red_add_v4(g_tmpA + (size_t)d * DD + c * 4, v);
}

// 7) tmpB = (tmpA * invI) @ W + b
//    thread = (row, 4-output-column group); W staged in smem.
__global__ void k_gemm(const float* __restrict__ W, const float* __restrict__ b) {
    __shared__ float Ws[DD * DD];
    __shared__ float bs[DD];
    for (int i = threadIdx.x; i < DD * DD; i += blockDim.x) Ws[i] = W[i];
    if (threadIdx.x < DD) bs[threadIdx.x] = b[threadIdx.x];
    __syncthreads();

    int tid = blockIdx.x * blockDim.x + threadIdx.x;
    if (tid >= NN * DV4) return;
    int n = tid >> 4;
    int jq = (tid & 15) * 4;
    float ii = g_invI[n];
    const float* row = g_tmpA + n * DD;
    float4 a = make_float4(bs[jq], bs[jq + 1], bs[jq + 2], bs[jq + 3]);
#pragma unroll
    for (int k = 0; k < DD; k++) {
        float xv = row[k] * ii;
        float4 w = *reinterpret_cast<const float4*>(Ws + k * DD + jq);
        a.x += xv * w.x; a.y += xv * w.y; a.z += xv * w.z; a.w += xv * w.w;
    }
    reinterpret_cast<float4*>(g_tmpB)[tid] = a;
}

// 8) final: out[dst] += h[src] * coef(e),  coef = 2 - (e&1)
__global__ void k_final_scatter(float* __restrict__ out,
                                const int* __restrict__ src, const int* __restrict__ dst,
                                const int* __restrict__ ef, int E) {
    int tid = blockIdx.x * blockDim.x + threadIdx.x;
    if (tid >= E * DV4) return;
    int e = tid >> 4, c = tid & 15;
    int s = __ldg(src + e);
    int d = __ldg(dst + e);
    float coef = (float)(2 - (__ldg(ef + e) & 1));
    float4 v = *(reinterpret_cast<const float4*>(g_tmpB) + s * DV4 + c);
    v.x *= coef; v.y *= coef; v.z *= coef; v.w *= coef;
    red_add_v4(out + (size_t)d * DD + c * 4, v);
}

extern "C" void kernel_launch(void* const* d_in, const int* in_sizes, int n_in,
                              void* d_out, int out_size) {
    const float4* x4 = (const float4*)d_in[0];   // graph_embedding [N,64]
    const float*  W  = (const float*)d_in[1];    // [64,64]
    const float*  b  = (const float*)d_in[2];    // [64]
    const int*    src = (const int*)d_in[3];     // [E]
    const int*    dst = (const int*)d_in[4];     // [E]
    const int*    ef  = (const int*)d_in[5];     // [E]
    float* out = (float*)d_out;

    const int E = in_sizes[3];

    const int TB = 256;
    int gN = (NN * DV4 + TB - 1) / TB;       // node*vec4 grid
    int gE1 = (E + TB - 1) / TB;             // per-edge grid
    int gE16 = (E * DV4 + TB - 1) / TB;      // edge*vec4 grid

    k_zero<<<gN, TB>>>((float4*)out);
    k_degree<<<gE1, TB>>>(src, dst, E);
    k_scale_x<<<gN, TB>>>(x4);
    k_scatter1<<<gE16, TB>>>(src, dst, E);   // tmpB += tmpA[src] -> dst
    k_rescale_rezero<<<gN, TB>>>();
    k_scatter2<<<gE16, TB>>>(src, dst, E);   // tmpA += tmpB[src] -> dst
    k_gemm<<<gN, TB>>>(W, b);
    k_final_scatter<<<gE16, TB>>>(out, src, dst, ef, E);
}

// round 3
// speedup vs baseline: 1.1732x; 1.1732x over previous
#include <cuda_runtime.h>
#include <stdint.h>

#define NN 50000            // nodes
#define DD 64               // feature dim
#define DV4 16              // float4s per row
#define EMAX 800000         // edges (fixed shape per reference)

// Scratch (device globals -- referenced ONLY inside device code)
__device__ float g_tmpA[NN * DD];
__device__ float g_tmpB[NN * DD];
__device__ float g_invO[NN];
__device__ float g_invI[NN];
__device__ int   g_degO[NN];
__device__ int   g_degI[NN];
__device__ int   g_rowptr[NN + 1];
__device__ int   g_cur[NN];
__device__ unsigned g_csr[EMAX];   // src | (ef&1)<<31

// ---------------------------------------------------------------------------
// 1) zero int degree counters
__global__ void k_init() {
    int i = blockIdx.x * blockDim.x + threadIdx.x;
    if (i < NN) { g_degO[i] = 0; g_degI[i] = 0; }
}

// 2) degrees (int atomics)
__global__ void k_degree(const int* __restrict__ src, const int* __restrict__ dst, int E) {
    int e = blockIdx.x * blockDim.x + threadIdx.x;
    if (e < E) {
        atomicAdd(&g_degO[src[e]], 1);
        atomicAdd(&g_degI[dst[e]], 1);
    }
}

// 3) exclusive prefix sum of in-degrees -> rowptr, cur  (single block, warp scans)
__global__ void k_scan() {
    __shared__ int warpsum[32];
    __shared__ int s_carry;
    int t = threadIdx.x, lane = t & 31, w = t >> 5;
    if (t == 0) s_carry = 0;
    __syncthreads();
    for (int base = 0; base < NN; base += 1024) {
        int i = base + t;
        int v = (i < NN) ? g_degI[i] : 0;
        int x = v;
#pragma unroll
        for (int o = 1; o < 32; o <<= 1) {
            int y = __shfl_up_sync(0xFFFFFFFFu, x, o);
            if (lane >= o) x += y;
        }
        if (lane == 31) warpsum[w] = x;
        __syncthreads();
        if (w == 0) {
            int s = warpsum[lane];
#pragma unroll
            for (int o = 1; o < 32; o <<= 1) {
                int y = __shfl_up_sync(0xFFFFFFFFu, s, o);
                if (lane >= o) s += y;
            }
            warpsum[lane] = s;
        }
        __syncthreads();
        int woff = (w > 0) ? warpsum[w - 1] : 0;
        int excl = x - v + woff + s_carry;
        if (i < NN) { g_rowptr[i] = excl; g_cur[i] = excl; }
        __syncthreads();                    // all s_carry reads done
        if (t == 0) s_carry += warpsum[31]; // chunk total
        __syncthreads();
    }
    if (t == 0) g_rowptr[NN] = s_carry;
}

// 4) bin edges into CSR-by-dst; pack coef bit (ef&1) into bit 31
__global__ void k_bin(const int* __restrict__ src, const int* __restrict__ dst,
                      const int* __restrict__ ef, int E) {
    int e = blockIdx.x * blockDim.x + threadIdx.x;
    if (e >= E) return;
    int d = dst[e];
    int pos = atomicAdd(&g_cur[d], 1);
    g_csr[pos] = (unsigned)src[e] | ((unsigned)(ef[e] & 1) << 31);
}

// 5) inv-sqrt degrees + tmpA = x * invO
__global__ void k_scale_x(const float4* __restrict__ x4) {
    int tid = blockIdx.x * blockDim.x + threadIdx.x;
    if (tid >= NN * DV4) return;
    int n = tid >> 4, c = tid & 15;
    float io = rsqrtf(fmaxf((float)g_degO[n], 1.0f));
    if (c == 0) {
        g_invO[n] = io;
        g_invI[n] = rsqrtf(fmaxf((float)g_degI[n], 1.0f));
    }
    float4 v = x4[tid];
    v.x *= io; v.y *= io; v.z *= io; v.w *= io;
    reinterpret_cast<float4*>(g_tmpA)[tid] = v;
}

// ---------------------------------------------------------------------------
// Pull aggregation: one warp per dst node. 16 lanes = 16 float4 columns;
// the two half-warps split the edge list, merged via shfl_xor(16).
// MODE 0: tmpB[d] = (sum tmpA[s]) * invI[d]*invO[d]
// MODE 1: tmpA[d] = (sum tmpB[s]) * invI[d]
// MODE 2: out[d]  =  sum coef_e * tmpB[s]
template <int MODE>
__global__ void k_pull(float4* __restrict__ outbuf) {
    int gid = blockIdx.x * blockDim.x + threadIdx.x;
    int node = gid >> 5;
    if (node >= NN) return;
    int lane = gid & 31;
    int col = lane & 15;
    int half = lane >> 4;

    const float4* srcb = reinterpret_cast<const float4*>(MODE == 0 ? g_tmpA : g_tmpB);
    int beg = g_rowptr[node];
    int end = g_rowptr[node + 1];

    float4 acc = make_float4(0.f, 0.f, 0.f, 0.f);
    int j = beg + half;
    // unrolled: 8 edges per warp-iteration (4 per half) -> MLP=4
    for (; j + 6 < end; j += 8) {
        unsigned v0 = g_csr[j], v1 = g_csr[j + 2], v2 = g_csr[j + 4], v3 = g_csr[j + 6];
        float4 a0 = srcb[(size_t)(v0 & 0x7FFFFFFFu) * DV4 + col];
        float4 a1 = srcb[(size_t)(v1 & 0x7FFFFFFFu) * DV4 + col];
        float4 a2 = srcb[(size_t)(v2 & 0x7FFFFFFFu) * DV4 + col];
        float4 a3 = srcb[(size_t)(v3 & 0x7FFFFFFFu) * DV4 + col];
        if (MODE == 2) {
            float c0 = (v0 >> 31) ? 1.f : 2.f, c1 = (v1 >> 31) ? 1.f : 2.f;
            float c2 = (v2 >> 31) ? 1.f : 2.f, c3 = (v3 >> 31) ? 1.f : 2.f;
            acc.x += a0.x*c0 + a1.x*c1 + a2.x*c2 + a3.x*c3;
            acc.y += a0.y*c0 + a1.y*c1 + a2.y*c2 + a3.y*c3;
            acc.z += a0.z*c0 + a1.z*c1 + a2.z*c2 + a3.z*c3;
            acc.w += a0.w*c0 + a1.w*c1 + a2.w*c2 + a3.w*c3;
        } else {
            acc.x += a0.x + a1.x + a2.x + a3.x;
            acc.y += a0.y + a1.y + a2.y + a3.y;
            acc.z += a0.z + a1.z + a2.z + a3.z;
            acc.w += a0.w + a1.w + a2.w + a3.w;
        }
    }
    for (; j < end; j += 2) {
        unsigned v = g_csr[j];
        float4 a = srcb[(size_t)(v & 0x7FFFFFFFu) * DV4 + col];
        float c = (MODE == 2) ? ((v >> 31) ? 1.f : 2.f) : 1.f;
        acc.x += a.x * c; acc.y += a.y * c; acc.z += a.z * c; acc.w += a.w * c;
    }
    // merge the two half-warps (same col, different edge subsets)
    acc.x += __shfl_xor_sync(0xFFFFFFFFu, acc.x, 16);
    acc.y += __shfl_xor_sync(0xFFFFFFFFu, acc.y, 16);
    acc.z += __shfl_xor_sync(0xFFFFFFFFu, acc.z, 16);
    acc.w += __shfl_xor_sync(0xFFFFFFFFu, acc.w, 16);

    if (half == 0) {
        float sc = 1.f;
        if (MODE == 0) sc = g_invI[node] * g_invO[node];
        if (MODE == 1) sc = g_invI[node];
        acc.x *= sc; acc.y *= sc; acc.z *= sc; acc.w *= sc;
        if (MODE == 0)
            reinterpret_cast<float4*>(g_tmpB)[node * DV4 + col] = acc;
        else if (MODE == 1)
            reinterpret_cast<float4*>(g_tmpA)[node * DV4 + col] = acc;
        else
            outbuf[node * DV4 + col] = acc;
    }
}

// 8) tmpB = tmpA @ W + b   (invI already folded into tmpA by pull<1>)
__global__ void k_gemm(const float* __restrict__ W, const float* __restrict__ b) {
    __shared__ float Ws[DD * DD];
    __shared__ float bs[DD];
    for (int i = threadIdx.x; i < DD * DD; i += blockDim.x) Ws[i] = W[i];
    if (threadIdx.x < DD) bs[threadIdx.x] = b[threadIdx.x];
    __syncthreads();

    int tid = blockIdx.x * blockDim.x + threadIdx.x;
    if (tid >= NN * DV4) return;
    int n = tid >> 4;
    int jq = (tid & 15) * 4;
    const float* row = g_tmpA + n * DD;
    float4 a = make_float4(bs[jq], bs[jq + 1], bs[jq + 2], bs[jq + 3]);
#pragma unroll
    for (int k = 0; k < DD; k++) {
        float xv = row[k];
        float4 w = *reinterpret_cast<const float4*>(Ws + k * DD + jq);
        a.x += xv * w.x; a.y += xv * w.y; a.z += xv * w.z; a.w += xv * w.w;
    }
    reinterpret_cast<float4*>(g_tmpB)[tid] = a;
}

extern "C" void kernel_launch(void* const* d_in, const int* in_sizes, int n_in,
                              void* d_out, int out_size) {
    const float4* x4  = (const float4*)d_in[0];
    const float*  W   = (const float*)d_in[1];
    const float*  b   = (const float*)d_in[2];
    const int*    src = (const int*)d_in[3];
    const int*    dst = (const int*)d_in[4];
    const int*    ef  = (const int*)d_in[5];
    float4* out = (float4*)d_out;

    const int E = in_sizes[3];
    const int TB = 256;
    int gNode = (NN + TB - 1) / TB;
    int gE    = (E + TB - 1) / TB;
    int gN16  = (NN * DV4 + TB - 1) / TB;
    int gWarp = (NN * 32 + TB - 1) / TB;   // one warp per node

    k_init<<<gNode, TB>>>();
    k_degree<<<gE, TB>>>(src, dst, E);
    k_scan<<<1, 1024>>>();
    k_bin<<<gE, TB>>>(src, dst, ef, E);
    k_scale_x<<<gN16, TB>>>(x4);
    k_pull<0><<<gWarp, TB>>>(nullptr);     // tmpB = norm * sum tmpA[src]
    k_pull<1><<<gWarp, TB>>>(nullptr);     // tmpA = invI * sum tmpB[src]
    k_gemm<<<gN16, TB>>>(W, b);
    k_pull<2><<<gWarp, TB>>>(out);         // out = sum coef * tmpB[src]
}